// round 6
// baseline (speedup 1.0000x reference)
#include <cuda_runtime.h>
#include <math.h>

#define S_DIM 512
#define B_DIM 32
#define T_DIM 1024
#define E_DIM 512
#define Q_DIM 128
#define SPB   16         // s-rows per consumer block
#define TCH   32         // t-chunk (weight tile width)
#define CUT   16.0f      // exponent cutoff: exp(-16) ~ 1.1e-7
#define NTHR  512

// Scratch (allocation-free rule: __device__ globals).
__device__ float2 g_ms[B_DIM * S_DIM];   // (mean, std), layout [b][s]
__device__ int    g_flag[B_DIM];         // 0 -> 1 when producer b done (monotone)

// Packed f32x2 helpers (Blackwell FFMA2 — only reachable via PTX).
static __device__ __forceinline__ unsigned long long pack2f(float a, float b) {
    unsigned long long r;
    asm("mov.b64 %0, {%1, %2};" : "=l"(r) : "f"(a), "f"(b));
    return r;
}
static __device__ __forceinline__ unsigned long long fma2(
    unsigned long long a, unsigned long long b, unsigned long long c) {
    unsigned long long d;
    asm("fma.rn.f32x2 %0, %1, %2, %3;" : "=l"(d) : "l"(a), "l"(b), "l"(c));
    return d;
}

// ---------------------------------------------------------------------------
// ONE fused kernel. Grid (B, 1 + S/SPB), 512 threads.
//   blockIdx.y == 0 : producer for batch b (16 warps x 32 rows) + scan.
//   blockIdx.y >= 1 : consumer chunk — windowed Gaussian context GEMM,
//                     thread tile 4 si x 4 e (group g=tid>>7 owns si 4g..4g+3).
// ---------------------------------------------------------------------------
__global__ void __launch_bounds__(NTHR) ga_fused(
    const float* __restrict__ q,     // [S,B,Q]
    const float* __restrict__ emb,   // [T,B,E]
    const float* __restrict__ mask,  // [T,B]
    const float* __restrict__ pos,   // [S,B]
    const float* __restrict__ W,     // [2,Q]
    const float* __restrict__ bias,  // [2]
    float* __restrict__ out_ctx,     // [S,B,E]
    float* __restrict__ out_mean)    // [S,B]
{
    const int b    = blockIdx.x;
    const int tid  = threadIdx.x;
    const int warp = tid >> 5;
    const int lane = tid & 31;

    if (blockIdx.y == 0) {
        // ================= PRODUCER (16 warps x 32 rows) =================
        __shared__ float p_mr[S_DIM];
        __shared__ float p_sd[S_DIM];
        __shared__ float wsum[16];

        float4 a0 = ((const float4*)W)[lane];
        float4 a1 = ((const float4*)W)[32 + lane];
        float b0 = bias[0], b1 = bias[1];

        #pragma unroll
        for (int g = 0; g < 4; g++) {
            int r0 = warp * 32 + g * 8;
            float v[16];
            #pragma unroll
            for (int k = 0; k < 8; k++) {
                int s = r0 + k;
                float4 x = ((const float4*)q)[((size_t)s * B_DIM + b) * 32 + lane];
                v[2 * k]     = x.x * a0.x + x.y * a0.y + x.z * a0.z + x.w * a0.w;
                v[2 * k + 1] = x.x * a1.x + x.y * a1.y + x.z * a1.z + x.w * a1.w;
            }
            // Multi-value butterfly: 16 sums reduced in 16 SHFLs.
            #pragma unroll
            for (int i = 0; i < 8; i++) {
                float send = (lane & 16) ? v[i] : v[i + 8];
                float recv = __shfl_xor_sync(0xFFFFFFFFu, send, 16);
                v[i] = ((lane & 16) ? v[i + 8] : v[i]) + recv;
            }
            #pragma unroll
            for (int i = 0; i < 4; i++) {
                float send = (lane & 8) ? v[i] : v[i + 4];
                float recv = __shfl_xor_sync(0xFFFFFFFFu, send, 8);
                v[i] = ((lane & 8) ? v[i + 4] : v[i]) + recv;
            }
            #pragma unroll
            for (int i = 0; i < 2; i++) {
                float send = (lane & 4) ? v[i] : v[i + 2];
                float recv = __shfl_xor_sync(0xFFFFFFFFu, send, 4);
                v[i] = ((lane & 4) ? v[i + 2] : v[i]) + recv;
            }
            {
                float send = (lane & 2) ? v[0] : v[1];
                float recv = __shfl_xor_sync(0xFFFFFFFFu, send, 2);
                v[0] = ((lane & 2) ? v[1] : v[0]) + recv;
            }
            v[0] += __shfl_xor_sync(0xFFFFFFFFu, v[0], 1);

            int m = (lane >> 1) & 15;   // value index: row k=m>>1, output j=m&1
            int k = m >> 1;
            int j = m & 1;
            float e = __expf(v[0] + (j ? b1 : b0));
            if (!(lane & 1)) {
                if (j == 0) p_mr[r0 + k] = e;
                else        p_sd[r0 + k] = e;
            }
        }
        __syncthreads();

        // Block-wide inclusive scan, one element per thread.
        float v = p_mr[tid];
        #pragma unroll
        for (int off = 1; off < 32; off <<= 1) {
            float y = __shfl_up_sync(0xFFFFFFFFu, v, off);
            if (lane >= off) v += y;
        }
        if (lane == 31) wsum[warp] = v;
        __syncthreads();
        if (warp == 0) {
            float w = (lane < 16) ? wsum[lane] : 0.0f;
            #pragma unroll
            for (int off = 1; off < 16; off <<= 1) {
                float y = __shfl_up_sync(0xFFFFFFFFu, w, off);
                if (lane >= off) w += y;
            }
            if (lane < 16) wsum[lane] = w;
        }
        __syncthreads();
        float base = warp ? wsum[warp - 1] : 0.0f;
        float mean = pos[(size_t)tid * B_DIM + b] + (base + v) * 0.05f;
        g_ms[b * S_DIM + tid] = make_float2(mean, p_sd[tid]);
        out_mean[(size_t)tid * B_DIM + b] = mean;

        __syncthreads();
        if (tid == 0) {
            __threadfence();
            asm volatile("st.release.gpu.global.b32 [%0], %1;"
                         :: "l"(&g_flag[b]), "r"(1) : "memory");
        }
        return;
    }

    // ================= CONSUMER =================
    const int s0 = (blockIdx.y - 1) * SPB;
    const int g  = tid >> 7;          // group 0..3 -> si 4g..4g+3
    const int h  = tid & 127;         // thread within group
    const int e0 = h * 4;             // this thread's 4 e-elements

    __shared__ float smean[SPB];
    __shared__ float sstd[SPB];
    __shared__ unsigned long long sw2[SPB][TCH];   // packed (w,w)

    if (tid == 0) {
        int f;
        do {
            asm volatile("ld.acquire.gpu.global.b32 %0, [%1];"
                         : "=r"(f) : "l"(&g_flag[b]) : "memory");
            if (!f) __nanosleep(64);
        } while (!f);
    }
    __syncthreads();

    if (tid < SPB) {
        float2 ms = g_ms[b * S_DIM + s0 + tid];
        smean[tid] = ms.x;
        sstd[tid]  = ms.y;
    }
    __syncthreads();

    // Union window over the SPB s-rows (uniform across block).
    int tlo = T_DIM, thi = -1;
    #pragma unroll
    for (int i = 0; i < SPB; i++) {
        float mean = smean[i];
        float hw   = sqrtf(CUT / sstd[i]);
        int lo = (int)fmaxf(0.0f, ceilf(mean - hw));
        int hi = (int)fminf((float)(T_DIM - 1), floorf(mean + hw));
        tlo = min(tlo, lo);
        thi = max(thi, hi);
    }

    ulonglong2 acc[4];
    #pragma unroll
    for (int i = 0; i < 4; i++) { acc[i].x = acc[i].y = 0ull; }

    const size_t rstride = (size_t)B_DIM * E_DIM;

    for (int tb = tlo; tb <= thi; tb += TCH) {
        int n = min(TCH, thi - tb + 1);
        __syncthreads();
        // Fill SPB*TCH = 512 weights: one per thread.
        {
            int si = tid >> 5;               // 0..15
            int tj = tid & (TCH - 1);
            float wv = 0.0f;
            if (tj < n) {
                int   t = tb + tj;
                float d = smean[si] - (float)t;
                wv = __expf(-sstd[si] * d * d) * mask[(size_t)t * B_DIM + b];
            }
            sw2[si][tj] = pack2f(wv, wv);
        }
        __syncthreads();

        const float* ep = emb + ((size_t)tb * B_DIM + b) * E_DIM + e0;
        ulonglong2 v = *(const ulonglong2*)ep;           // row j in regs
        for (int j = 0; j < n; j++) {
            ep += rstride;
            ulonglong2 vn = v;
            if (j + 1 < n) vn = *(const ulonglong2*)ep;  // prefetch next row
            #pragma unroll
            for (int r = 0; r < 4; r++) {
                unsigned long long w2 = sw2[g * 4 + r][j];   // broadcast LDS.64
                acc[r].x = fma2(v.x, w2, acc[r].x);
                acc[r].y = fma2(v.y, w2, acc[r].y);
            }
            v = vn;
        }
    }

    #pragma unroll
    for (int r = 0; r < 4; r++) {
        float* op = out_ctx + ((size_t)(s0 + g * 4 + r) * B_DIM + b) * E_DIM + e0;
        *(ulonglong2*)op = acc[r];
    }
}

// ---------------------------------------------------------------------------
extern "C" void kernel_launch(void* const* d_in, const int* in_sizes, int n_in,
                              void* d_out, int out_size) {
    const float* query = (const float*)d_in[0];  // [S,B,Q]
    const float* emb   = (const float*)d_in[1];  // [T,B,E]
    const float* mask  = (const float*)d_in[2];  // [T,B]
    const float* pos   = (const float*)d_in[3];  // [S,B]
    const float* W     = (const float*)d_in[4];  // [2,Q]
    const float* bias  = (const float*)d_in[5];  // [2]

    float* out_ctx  = (float*)d_out;                                  // [S,B,E]
    float* out_mean = (float*)d_out + (size_t)S_DIM * B_DIM * E_DIM;  // [S,B]

    dim3 grid(B_DIM, 1 + S_DIM / SPB);   // 32 producers first, 1024 consumers
    ga_fused<<<grid, NTHR>>>(query, emb, mask, pos, W, bias, out_ctx, out_mean);
}

// round 7
// speedup vs baseline: 1.2130x; 1.2130x over previous
#include <cuda_runtime.h>
#include <math.h>

#define S_DIM 512
#define B_DIM 32
#define T_DIM 1024
#define E_DIM 512
#define Q_DIM 128
#define SPB   16         // s-rows per consumer block
#define TCH   32         // t-chunk (weight tile width)
#define CUT   16.0f      // exponent cutoff: exp(-16) ~ 1.1e-7
#define QCH   128        // s-rows per producer quarter
#define NQ    4          // producer quarters per batch
#define PRE_T 64         // prefetch this many t-rows per consumer

// Scratch (allocation-free rule: __device__ globals).
__device__ float2 g_ms[B_DIM * S_DIM];     // (mean, std), [b][s]
__device__ float  g_qtot[B_DIM * NQ];      // cumulative sum through quarter q
__device__ int    g_qflag[B_DIM * NQ];     // 0 -> 1 (monotone) per (b, quarter)

// Packed f32x2 helpers (Blackwell FFMA2 — only reachable via PTX).
static __device__ __forceinline__ unsigned long long pack2f(float a, float b) {
    unsigned long long r;
    asm("mov.b64 %0, {%1, %2};" : "=l"(r) : "f"(a), "f"(b));
    return r;
}
static __device__ __forceinline__ unsigned long long fma2(
    unsigned long long a, unsigned long long b, unsigned long long c) {
    unsigned long long d;
    asm("fma.rn.f32x2 %0, %1, %2, %3;" : "=l"(d) : "l"(a), "l"(b), "l"(c));
    return d;
}
static __device__ __forceinline__ int ld_acq(const int* p) {
    int v;
    asm volatile("ld.acquire.gpu.global.b32 %0, [%1];" : "=r"(v) : "l"(p) : "memory");
    return v;
}
static __device__ __forceinline__ void st_rel(int* p, int v) {
    asm volatile("st.release.gpu.global.b32 [%0], %1;" :: "l"(p), "r"(v) : "memory");
}

// ---------------------------------------------------------------------------
// ONE fused kernel. Grid (B, NQ + 64), 128 threads.
//  y in [0,NQ)  : producer quarter y for batch b (dots + exp + chained scan).
//  y >= NQ      : consumer — chunk cy=(y-NQ): s0=(cy>>1)*SPB, e-half (cy&1).
// ---------------------------------------------------------------------------
__global__ void __launch_bounds__(128) ga_fused(
    const float* __restrict__ q,     // [S,B,Q]
    const float* __restrict__ emb,   // [T,B,E]
    const float* __restrict__ mask,  // [T,B]
    const float* __restrict__ pos,   // [S,B]
    const float* __restrict__ W,     // [2,Q]
    const float* __restrict__ bias,  // [2]
    float* __restrict__ out_ctx,     // [S,B,E]
    float* __restrict__ out_mean)    // [S,B]
{
    const int b    = blockIdx.x;
    const int tid  = threadIdx.x;
    const int warp = tid >> 5;
    const int lane = tid & 31;

    if (blockIdx.y < NQ) {
        // ================= PRODUCER quarter =================
        const int quarter = blockIdx.y;
        const int s_base  = quarter * QCH;

        __shared__ float p_mr[QCH];
        __shared__ float p_sd[QCH];
        __shared__ float wsum[4];
        __shared__ float sprev;

        float4 a0 = ((const float4*)W)[lane];
        float4 a1 = ((const float4*)W)[32 + lane];
        float b0 = bias[0], b1 = bias[1];

        // Warp owns rows [warp*32, warp*32+32) of the quarter, in groups of 8.
        #pragma unroll
        for (int g = 0; g < 4; g++) {
            int r0 = warp * 32 + g * 8;
            float v[16];
            #pragma unroll
            for (int k = 0; k < 8; k++) {
                int s = s_base + r0 + k;
                float4 x = ((const float4*)q)[((size_t)s * B_DIM + b) * 32 + lane];
                v[2 * k]     = x.x * a0.x + x.y * a0.y + x.z * a0.z + x.w * a0.w;
                v[2 * k + 1] = x.x * a1.x + x.y * a1.y + x.z * a1.z + x.w * a1.w;
            }
            // Multi-value butterfly: 16 sums reduced in 16 SHFLs.
            #pragma unroll
            for (int i = 0; i < 8; i++) {
                float send = (lane & 16) ? v[i] : v[i + 8];
                float recv = __shfl_xor_sync(0xFFFFFFFFu, send, 16);
                v[i] = ((lane & 16) ? v[i + 8] : v[i]) + recv;
            }
            #pragma unroll
            for (int i = 0; i < 4; i++) {
                float send = (lane & 8) ? v[i] : v[i + 4];
                float recv = __shfl_xor_sync(0xFFFFFFFFu, send, 8);
                v[i] = ((lane & 8) ? v[i + 4] : v[i]) + recv;
            }
            #pragma unroll
            for (int i = 0; i < 2; i++) {
                float send = (lane & 4) ? v[i] : v[i + 2];
                float recv = __shfl_xor_sync(0xFFFFFFFFu, send, 4);
                v[i] = ((lane & 4) ? v[i + 2] : v[i]) + recv;
            }
            {
                float send = (lane & 2) ? v[0] : v[1];
                float recv = __shfl_xor_sync(0xFFFFFFFFu, send, 2);
                v[0] = ((lane & 2) ? v[1] : v[0]) + recv;
            }
            v[0] += __shfl_xor_sync(0xFFFFFFFFu, v[0], 1);

            int m = (lane >> 1) & 15;     // row k=m>>1, output j=m&1
            int k = m >> 1;
            int j = m & 1;
            float e = __expf(v[0] + (j ? b1 : b0));
            if (!(lane & 1)) {
                if (j == 0) p_mr[r0 + k] = e;
                else        p_sd[r0 + k] = e;
            }
        }
        __syncthreads();

        // In-quarter inclusive scan (128 values, 4 warps).
        float v = p_mr[tid];
        #pragma unroll
        for (int off = 1; off < 32; off <<= 1) {
            float y = __shfl_up_sync(0xFFFFFFFFu, v, off);
            if (lane >= off) v += y;
        }
        if (lane == 31) wsum[warp] = v;
        __syncthreads();
        float base = 0.0f;
        #pragma unroll
        for (int w = 0; w < 3; w++) if (w < warp) base += wsum[w];
        float incl = base + v;

        // Previous quarters' cumulative total (chained hand-off).
        if (tid == 0) {
            float prev = 0.0f;
            if (quarter > 0) {
                while (!ld_acq(&g_qflag[b * NQ + quarter - 1])) __nanosleep(32);
                prev = g_qtot[b * NQ + quarter - 1];
            }
            sprev = prev;
        }
        __syncthreads();
        float qprev = sprev;

        int s = s_base + tid;
        float mean = pos[(size_t)s * B_DIM + b] + (qprev + incl) * 0.05f;
        g_ms[b * S_DIM + s] = make_float2(mean, p_sd[tid]);
        out_mean[(size_t)s * B_DIM + b] = mean;

        __syncthreads();
        if (tid == 0) {
            g_qtot[b * NQ + quarter] = qprev + wsum[0] + wsum[1] + wsum[2] + wsum[3];
            __threadfence();
            st_rel(&g_qflag[b * NQ + quarter], 1);
        }
        return;
    }

    // ================= CONSUMER =================
    const int cy   = blockIdx.y - NQ;       // 0..63
    const int s0   = (cy >> 1) * SPB;       // s-chunk
    const int eh   = (cy & 1) * 256;        // e-half offset
    const int half = tid >> 6;              // 0: si 0-7, 1: si 8-15
    const int h    = tid & 63;
    const int e0   = eh + h * 4;            // this thread's 4 e-elements
    const int quarter = s0 >> 7;

    __shared__ float smean[SPB];
    __shared__ float sstd[SPB];
    __shared__ unsigned long long sw2[SPB][TCH];   // packed (w,w)

    // Warm L2 with the (practically certain) active slab while producer runs.
    #pragma unroll
    for (int i = 0; i < 4; i++) {
        int line = tid + i * 128;           // 512 lines = 64 rows x 1KB half
        int t    = line >> 3;
        int off  = (line & 7) * 32;         // floats within the 1KB half
        const float* p = emb + ((size_t)t * B_DIM + b) * E_DIM + eh + off;
        asm volatile("prefetch.global.L2 [%0];" :: "l"(p));
    }

    if (tid == 0) {
        while (!ld_acq(&g_qflag[b * NQ + quarter])) __nanosleep(64);
    }
    __syncthreads();

    if (tid < SPB) {
        float2 ms = g_ms[b * S_DIM + s0 + tid];
        smean[tid] = ms.x;
        sstd[tid]  = ms.y;
    }
    __syncthreads();

    // Warp-parallel union window: lane si=lane&15, shfl min/max reduce.
    int tlo, thi;
    {
        int si = lane & 15;
        float mean = smean[si];
        float hw   = sqrtf(CUT / sstd[si]);
        int lo = (int)fmaxf(0.0f, ceilf(mean - hw));
        int hi = (int)fminf((float)(T_DIM - 1), floorf(mean + hw));
        #pragma unroll
        for (int off = 8; off; off >>= 1) {
            lo = min(lo, __shfl_xor_sync(0xFFFFFFFFu, lo, off));
            hi = max(hi, __shfl_xor_sync(0xFFFFFFFFu, hi, off));
        }
        tlo = lo; thi = hi;
    }

    ulonglong2 acc[8];
    #pragma unroll
    for (int i = 0; i < 8; i++) { acc[i].x = acc[i].y = 0ull; }

    const size_t rstride = (size_t)B_DIM * E_DIM;

    for (int tb = tlo; tb <= thi; tb += TCH) {
        int n = min(TCH, thi - tb + 1);
        __syncthreads();
        // Fill SPB*TCH = 512 weights: 128 threads x 4.
        #pragma unroll
        for (int i = 0; i < 4; i++) {
            int idx = tid + i * 128;
            int si  = idx >> 5;
            int tj  = idx & (TCH - 1);
            float wv = 0.0f;
            if (tj < n) {
                int   t = tb + tj;
                float d = smean[si] - (float)t;
                wv = __expf(-sstd[si] * d * d) * mask[(size_t)t * B_DIM + b];
            }
            sw2[si][tj] = pack2f(wv, wv);
        }
        __syncthreads();

        const float* ep = emb + ((size_t)tb * B_DIM + b) * E_DIM + e0;
        ulonglong2 v = *(const ulonglong2*)ep;           // row j in regs
        for (int j = 0; j < n; j++) {
            ep += rstride;
            ulonglong2 vn = v;
            if (j + 1 < n) vn = *(const ulonglong2*)ep;  // prefetch next row
            #pragma unroll
            for (int r = 0; r < 8; r++) {
                unsigned long long w2 = sw2[half * 8 + r][j];  // broadcast LDS.64
                acc[r].x = fma2(v.x, w2, acc[r].x);
                acc[r].y = fma2(v.y, w2, acc[r].y);
            }
            v = vn;
        }
    }

    #pragma unroll
    for (int r = 0; r < 8; r++) {
        float* op = out_ctx + ((size_t)(s0 + half * 8 + r) * B_DIM + b) * E_DIM + e0;
        *(ulonglong2*)op = acc[r];
    }
}

// ---------------------------------------------------------------------------
extern "C" void kernel_launch(void* const* d_in, const int* in_sizes, int n_in,
                              void* d_out, int out_size) {
    const float* query = (const float*)d_in[0];  // [S,B,Q]
    const float* emb   = (const float*)d_in[1];  // [T,B,E]
    const float* mask  = (const float*)d_in[2];  // [T,B]
    const float* pos   = (const float*)d_in[3];  // [S,B]
    const float* W     = (const float*)d_in[4];  // [2,Q]
    const float* bias  = (const float*)d_in[5];  // [2]

    float* out_ctx  = (float*)d_out;                                  // [S,B,E]
    float* out_mean = (float*)d_out + (size_t)S_DIM * B_DIM * E_DIM;  // [S,B]

    // y: 4 producer quarters, then 64 consumers (32 s-chunks x 2 e-halves).
    dim3 grid(B_DIM, NQ + (S_DIM / SPB) * 2);
    ga_fused<<<grid, 128>>>(query, emb, mask, pos, W, bias, out_ctx, out_mean);
}

// round 8
// speedup vs baseline: 1.3249x; 1.0923x over previous
#include <cuda_runtime.h>
#include <math.h>

#define S_DIM 512
#define B_DIM 32
#define T_DIM 1024
#define E_DIM 512
#define Q_DIM 128
#define SPB   16         // s-rows per consumer block
#define TCH   16         // staged t-chunk (rows in shared)
#define CUT   16.0f      // exponent cutoff: exp(-16) ~ 1.1e-7
#define QCH   128        // s-rows per producer quarter
#define NQ    4          // producer quarters per batch
#define NTHR  256

// Scratch (allocation-free rule: __device__ globals).
__device__ float2 g_ms[B_DIM * S_DIM];     // (mean, std), [b][s]
__device__ float  g_qsum[B_DIM * NQ];      // own-quarter mean_raw total
__device__ int    g_ftot[B_DIM * NQ];      // quarter total published (monotone)
__device__ int    g_fdone[B_DIM * NQ];     // quarter means written (monotone)

// Packed f32x2 helpers (Blackwell FFMA2 — only reachable via PTX).
static __device__ __forceinline__ unsigned long long pack2f(float a, float b) {
    unsigned long long r;
    asm("mov.b64 %0, {%1, %2};" : "=l"(r) : "f"(a), "f"(b));
    return r;
}
static __device__ __forceinline__ unsigned long long fma2(
    unsigned long long a, unsigned long long b, unsigned long long c) {
    unsigned long long d;
    asm("fma.rn.f32x2 %0, %1, %2, %3;" : "=l"(d) : "l"(a), "l"(b), "l"(c));
    return d;
}
static __device__ __forceinline__ int ld_acq(const int* p) {
    int v;
    asm volatile("ld.acquire.gpu.global.b32 %0, [%1];" : "=r"(v) : "l"(p) : "memory");
    return v;
}
static __device__ __forceinline__ void st_rel(int* p, int v) {
    asm volatile("st.release.gpu.global.b32 [%0], %1;" :: "l"(p), "r"(v) : "memory");
}
static __device__ __forceinline__ void cp_async16(unsigned smem_addr, const void* g) {
    asm volatile("cp.async.ca.shared.global [%0], [%1], 16;"
                 :: "r"(smem_addr), "l"(g) : "memory");
}

// ---------------------------------------------------------------------------
// ONE fused kernel. Grid (B, NQ + S/SPB), 256 threads.
//  y in [0,NQ) : producer quarter (dots + exp + parallel-total scan).
//  y >= NQ     : consumer — s-chunk (y-NQ), full E, smem-staged window GEMM.
// ---------------------------------------------------------------------------
__global__ void __launch_bounds__(NTHR) ga_fused(
    const float* __restrict__ q,     // [S,B,Q]
    const float* __restrict__ emb,   // [T,B,E]
    const float* __restrict__ mask,  // [T,B]
    const float* __restrict__ pos,   // [S,B]
    const float* __restrict__ W,     // [2,Q]
    const float* __restrict__ bias,  // [2]
    float* __restrict__ out_ctx,     // [S,B,E]
    float* __restrict__ out_mean)    // [S,B]
{
    const int b    = blockIdx.x;
    const int tid  = threadIdx.x;
    const int warp = tid >> 5;
    const int lane = tid & 31;

    if (blockIdx.y < NQ) {
        // ================= PRODUCER quarter (8 warps x 16 rows) ===========
        const int quarter = blockIdx.y;
        const int s_base  = quarter * QCH;

        __shared__ float p_mr[QCH];
        __shared__ float p_sd[QCH];
        __shared__ float wsum[4];
        __shared__ float sprev;

        float4 a0 = ((const float4*)W)[lane];
        float4 a1 = ((const float4*)W)[32 + lane];
        float b0 = bias[0], b1 = bias[1];

        #pragma unroll
        for (int g = 0; g < 2; g++) {
            int r0 = warp * 16 + g * 8;
            float v[16];
            #pragma unroll
            for (int k = 0; k < 8; k++) {
                int s = s_base + r0 + k;
                float4 x = ((const float4*)q)[((size_t)s * B_DIM + b) * 32 + lane];
                v[2 * k]     = x.x * a0.x + x.y * a0.y + x.z * a0.z + x.w * a0.w;
                v[2 * k + 1] = x.x * a1.x + x.y * a1.y + x.z * a1.z + x.w * a1.w;
            }
            // Multi-value butterfly: 16 sums reduced in 16 SHFLs.
            #pragma unroll
            for (int i = 0; i < 8; i++) {
                float send = (lane & 16) ? v[i] : v[i + 8];
                float recv = __shfl_xor_sync(0xFFFFFFFFu, send, 16);
                v[i] = ((lane & 16) ? v[i + 8] : v[i]) + recv;
            }
            #pragma unroll
            for (int i = 0; i < 4; i++) {
                float send = (lane & 8) ? v[i] : v[i + 4];
                float recv = __shfl_xor_sync(0xFFFFFFFFu, send, 8);
                v[i] = ((lane & 8) ? v[i + 4] : v[i]) + recv;
            }
            #pragma unroll
            for (int i = 0; i < 2; i++) {
                float send = (lane & 4) ? v[i] : v[i + 2];
                float recv = __shfl_xor_sync(0xFFFFFFFFu, send, 4);
                v[i] = ((lane & 4) ? v[i + 2] : v[i]) + recv;
            }
            {
                float send = (lane & 2) ? v[0] : v[1];
                float recv = __shfl_xor_sync(0xFFFFFFFFu, send, 2);
                v[0] = ((lane & 2) ? v[1] : v[0]) + recv;
            }
            v[0] += __shfl_xor_sync(0xFFFFFFFFu, v[0], 1);

            int m = (lane >> 1) & 15;     // row k=m>>1, output j=m&1
            int k = m >> 1;
            int j = m & 1;
            float e = __expf(v[0] + (j ? b1 : b0));
            if (!(lane & 1)) {
                if (j == 0) p_mr[r0 + k] = e;
                else        p_sd[r0 + k] = e;
            }
        }
        __syncthreads();

        // In-quarter scan on threads 0-127.
        float v = 0.0f;
        if (tid < QCH) {
            v = p_mr[tid];
            #pragma unroll
            for (int off = 1; off < 32; off <<= 1) {
                float y = __shfl_up_sync(0xFFFFFFFFu, v, off);
                if (lane >= off) v += y;
            }
            if (lane == 31) wsum[warp] = v;
        }
        __syncthreads();

        // Publish own total immediately; then gather previous quarters.
        if (tid == 0) {
            float tot = wsum[0] + wsum[1] + wsum[2] + wsum[3];
            g_qsum[b * NQ + quarter] = tot;
            __threadfence();
            st_rel(&g_ftot[b * NQ + quarter], 1);
            float prev = 0.0f;
            for (int qq = 0; qq < quarter; qq++) {
                while (!ld_acq(&g_ftot[b * NQ + qq])) __nanosleep(32);
                prev += g_qsum[b * NQ + qq];
            }
            sprev = prev;
        }
        __syncthreads();

        if (tid < QCH) {
            float base = sprev;
            #pragma unroll
            for (int w = 0; w < 3; w++) if (w < warp) base += wsum[w];
            int s = s_base + tid;
            float mean = pos[(size_t)s * B_DIM + b] + (base + v) * 0.05f;
            g_ms[b * S_DIM + s] = make_float2(mean, p_sd[tid]);
            out_mean[(size_t)s * B_DIM + b] = mean;
        }
        __syncthreads();
        if (tid == 0) {
            __threadfence();
            st_rel(&g_fdone[b * NQ + quarter], 1);
        }
        return;
    }

    // ================= CONSUMER =================
    const int s0      = (blockIdx.y - NQ) * SPB;
    const int half    = tid >> 7;         // 0: si 0-7, 1: si 8-15
    const int h       = tid & 127;        // e-slot: floats [4h, 4h+4)
    const int quarter = s0 >> 7;

    __shared__ float tile[TCH * E_DIM];               // 32 KB staged rows
    __shared__ float smean[SPB];
    __shared__ float sstd[SPB];
    __shared__ unsigned long long sw2[SPB][TCH];      // packed (w,w)

    // Warm L2 with rows [0,64) x full E while producers run.
    #pragma unroll
    for (int i = 0; i < 4; i++) {
        int line = tid + i * NTHR;        // 1024 x 128B lines
        int t    = line >> 4;
        int off  = (line & 15) * 32;
        const float* p = emb + ((size_t)t * B_DIM + b) * E_DIM + off;
        asm volatile("prefetch.global.L2 [%0];" :: "l"(p));
    }

    if (tid == 0) {
        while (!ld_acq(&g_fdone[b * NQ + quarter])) __nanosleep(64);
    }
    __syncthreads();

    if (tid < SPB) {
        float2 ms = g_ms[b * S_DIM + s0 + tid];
        smean[tid] = ms.x;
        sstd[tid]  = ms.y;
    }
    __syncthreads();

    // Warp-parallel union window (lane si=lane&15, shfl min/max reduce).
    int tlo, thi;
    {
        int si = lane & 15;
        float mean = smean[si];
        float hw   = sqrtf(CUT / sstd[si]);
        int lo = (int)fmaxf(0.0f, ceilf(mean - hw));
        int hi = (int)fminf((float)(T_DIM - 1), floorf(mean + hw));
        #pragma unroll
        for (int off = 8; off; off >>= 1) {
            lo = min(lo, __shfl_xor_sync(0xFFFFFFFFu, lo, off));
            hi = max(hi, __shfl_xor_sync(0xFFFFFFFFu, hi, off));
        }
        tlo = lo; thi = hi;
    }

    ulonglong2 acc[8];
    #pragma unroll
    for (int i = 0; i < 8; i++) { acc[i].x = acc[i].y = 0ull; }

    const size_t rstride = (size_t)B_DIM * E_DIM;
    const unsigned tile_base = (unsigned)__cvta_generic_to_shared(tile);

    for (int tb = tlo; tb <= thi; tb += TCH) {
        int n = min(TCH, thi - tb + 1);
        __syncthreads();   // protect tile + sw2 reuse across chunks

        // Stage n rows (2 KB each) into shared: threads split row-pairs,
        // 16B per cp.async, all copies in flight at once.
        for (int j = half; j < n; j += 2) {
            const float* src = emb + ((size_t)(tb + j) * B_DIM + b) * E_DIM + h * 4;
            cp_async16(tile_base + (unsigned)(j * E_DIM + h * 4) * 4u, src);
        }
        asm volatile("cp.async.commit_group;" ::: "memory");

        // Weights (independent of staged data — overlaps the copies).
        {
            int si = tid >> 4;                // 0..15
            int tj = tid & (TCH - 1);
            float wv = 0.0f;
            if (tj < n) {
                int   t = tb + tj;
                float d = smean[si] - (float)t;
                wv = __expf(-sstd[si] * d * d) * mask[(size_t)t * B_DIM + b];
            }
            sw2[si][tj] = pack2f(wv, wv);
        }

        asm volatile("cp.async.wait_group 0;" ::: "memory");
        __syncthreads();

        // FMA entirely from shared: LDS.128 row slice + 8 broadcast LDS.64.
        #pragma unroll 4
        for (int j = 0; j < n; j++) {
            ulonglong2 v = *(const ulonglong2*)&tile[j * E_DIM + h * 4];
            #pragma unroll
            for (int r = 0; r < 8; r++) {
                unsigned long long w2 = sw2[half * 8 + r][j];
                acc[r].x = fma2(v.x, w2, acc[r].x);
                acc[r].y = fma2(v.y, w2, acc[r].y);
            }
        }
    }

    #pragma unroll
    for (int r = 0; r < 8; r++) {
        float* op = out_ctx + ((size_t)(s0 + half * 8 + r) * B_DIM + b) * E_DIM + h * 4;
        *(ulonglong2*)op = acc[r];
    }
}

// ---------------------------------------------------------------------------
extern "C" void kernel_launch(void* const* d_in, const int* in_sizes, int n_in,
                              void* d_out, int out_size) {
    const float* query = (const float*)d_in[0];  // [S,B,Q]
    const float* emb   = (const float*)d_in[1];  // [T,B,E]
    const float* mask  = (const float*)d_in[2];  // [T,B]
    const float* pos   = (const float*)d_in[3];  // [S,B]
    const float* W     = (const float*)d_in[4];  // [2,Q]
    const float* bias  = (const float*)d_in[5];  // [2]

    float* out_ctx  = (float*)d_out;                                  // [S,B,E]
    float* out_mean = (float*)d_out + (size_t)S_DIM * B_DIM * E_DIM;  // [S,B]

    dim3 grid(B_DIM, NQ + S_DIM / SPB);   // 128 producers, 1024 consumers
    ga_fused<<<grid, NTHR>>>(query, emb, mask, pos, W, bias, out_ctx, out_mean);
}

// round 9
// speedup vs baseline: 1.7703x; 1.3361x over previous
#include <cuda_runtime.h>
#include <math.h>

#define S_DIM 512
#define B_DIM 32
#define T_DIM 1024
#define E_DIM 512
#define Q_DIM 128
#define SPB   16         // s-rows per consumer block
#define TCH   16         // staged t-chunk (rows in shared)
#define CUT   16.0f      // exponent cutoff: exp(-16) ~ 1.1e-7
#define QCH   128        // s-rows per producer quarter
#define NQ    4          // producer quarters per batch
#define NTHR  256

// Scratch (allocation-free rule: __device__ globals).
__device__ float2 g_ms[B_DIM * S_DIM];     // (mean, std), [b][s]
__device__ float  g_qsum[B_DIM * NQ];      // own-quarter mean_raw total
__device__ int    g_ftot[B_DIM * NQ];      // quarter total published (monotone)
__device__ int    g_fdone[B_DIM * NQ];     // quarter means written (monotone)

// Packed f32x2 helpers (Blackwell FFMA2 — only reachable via PTX).
static __device__ __forceinline__ unsigned long long pack2f(float a, float b) {
    unsigned long long r;
    asm("mov.b64 %0, {%1, %2};" : "=l"(r) : "f"(a), "f"(b));
    return r;
}
static __device__ __forceinline__ unsigned long long fma2(
    unsigned long long a, unsigned long long b, unsigned long long c) {
    unsigned long long d;
    asm("fma.rn.f32x2 %0, %1, %2, %3;" : "=l"(d) : "l"(a), "l"(b), "l"(c));
    return d;
}
static __device__ __forceinline__ int ld_acq(const int* p) {
    int v;
    asm volatile("ld.acquire.gpu.global.b32 %0, [%1];" : "=r"(v) : "l"(p) : "memory");
    return v;
}
static __device__ __forceinline__ void st_rel(int* p, int v) {
    asm volatile("st.release.gpu.global.b32 [%0], %1;" :: "l"(p), "r"(v) : "memory");
}
static __device__ __forceinline__ void cp_async16(unsigned smem_addr, const void* g) {
    asm volatile("cp.async.ca.shared.global [%0], [%1], 16;"
                 :: "r"(smem_addr), "l"(g) : "memory");
}

// ---------------------------------------------------------------------------
// ONE fused kernel. Grid (B, NQ + S/SPB), 256 threads, 4 blocks/SM forced.
//  y in [0,NQ) : producer quarter (dots + exp + parallel-total scan).
//  y >= NQ     : consumer — s-chunk (y-NQ), full E, smem-staged window GEMM.
// ---------------------------------------------------------------------------
__global__ void __launch_bounds__(NTHR, 4) ga_fused(
    const float* __restrict__ q,     // [S,B,Q]
    const float* __restrict__ emb,   // [T,B,E]
    const float* __restrict__ mask,  // [T,B]
    const float* __restrict__ pos,   // [S,B]
    const float* __restrict__ W,     // [2,Q]
    const float* __restrict__ bias,  // [2]
    float* __restrict__ out_ctx,     // [S,B,E]
    float* __restrict__ out_mean)    // [S,B]
{
    const int b    = blockIdx.x;
    const int tid  = threadIdx.x;
    const int warp = tid >> 5;
    const int lane = tid & 31;

    if (blockIdx.y < NQ) {
        // ================= PRODUCER quarter (8 warps x 16 rows) ===========
        const int quarter = blockIdx.y;
        const int s_base  = quarter * QCH;

        __shared__ float p_mr[QCH];
        __shared__ float p_sd[QCH];
        __shared__ float wsum[4];
        __shared__ float sprev;

        float4 a0 = ((const float4*)W)[lane];
        float4 a1 = ((const float4*)W)[32 + lane];
        float b0 = bias[0], b1 = bias[1];

        #pragma unroll
        for (int g = 0; g < 2; g++) {
            int r0 = warp * 16 + g * 8;
            float v[16];
            #pragma unroll
            for (int k = 0; k < 8; k++) {
                int s = s_base + r0 + k;
                float4 x = ((const float4*)q)[((size_t)s * B_DIM + b) * 32 + lane];
                v[2 * k]     = x.x * a0.x + x.y * a0.y + x.z * a0.z + x.w * a0.w;
                v[2 * k + 1] = x.x * a1.x + x.y * a1.y + x.z * a1.z + x.w * a1.w;
            }
            // Multi-value butterfly: 16 sums reduced in 16 SHFLs.
            #pragma unroll
            for (int i = 0; i < 8; i++) {
                float send = (lane & 16) ? v[i] : v[i + 8];
                float recv = __shfl_xor_sync(0xFFFFFFFFu, send, 16);
                v[i] = ((lane & 16) ? v[i + 8] : v[i]) + recv;
            }
            #pragma unroll
            for (int i = 0; i < 4; i++) {
                float send = (lane & 8) ? v[i] : v[i + 4];
                float recv = __shfl_xor_sync(0xFFFFFFFFu, send, 8);
                v[i] = ((lane & 8) ? v[i + 4] : v[i]) + recv;
            }
            #pragma unroll
            for (int i = 0; i < 2; i++) {
                float send = (lane & 4) ? v[i] : v[i + 2];
                float recv = __shfl_xor_sync(0xFFFFFFFFu, send, 4);
                v[i] = ((lane & 4) ? v[i + 2] : v[i]) + recv;
            }
            {
                float send = (lane & 2) ? v[0] : v[1];
                float recv = __shfl_xor_sync(0xFFFFFFFFu, send, 2);
                v[0] = ((lane & 2) ? v[1] : v[0]) + recv;
            }
            v[0] += __shfl_xor_sync(0xFFFFFFFFu, v[0], 1);

            int m = (lane >> 1) & 15;     // row k=m>>1, output j=m&1
            int k = m >> 1;
            int j = m & 1;
            float e = __expf(v[0] + (j ? b1 : b0));
            if (!(lane & 1)) {
                if (j == 0) p_mr[r0 + k] = e;
                else        p_sd[r0 + k] = e;
            }
        }
        __syncthreads();

        // In-quarter scan on threads 0-127.
        float v = 0.0f;
        if (tid < QCH) {
            v = p_mr[tid];
            #pragma unroll
            for (int off = 1; off < 32; off <<= 1) {
                float y = __shfl_up_sync(0xFFFFFFFFu, v, off);
                if (lane >= off) v += y;
            }
            if (lane == 31) wsum[warp] = v;
        }
        __syncthreads();

        // Publish own total immediately; then gather previous quarters.
        if (tid == 0) {
            float tot = wsum[0] + wsum[1] + wsum[2] + wsum[3];
            g_qsum[b * NQ + quarter] = tot;
            __threadfence();
            st_rel(&g_ftot[b * NQ + quarter], 1);
            float prev = 0.0f;
            for (int qq = 0; qq < quarter; qq++) {
                while (!ld_acq(&g_ftot[b * NQ + qq])) __nanosleep(32);
                prev += g_qsum[b * NQ + qq];
            }
            sprev = prev;
        }
        __syncthreads();

        if (tid < QCH) {
            float base = sprev;
            #pragma unroll
            for (int w = 0; w < 3; w++) if (w < warp) base += wsum[w];
            int s = s_base + tid;
            float mean = pos[(size_t)s * B_DIM + b] + (base + v) * 0.05f;
            g_ms[b * S_DIM + s] = make_float2(mean, p_sd[tid]);
            out_mean[(size_t)s * B_DIM + b] = mean;
        }
        __syncthreads();
        if (tid == 0) {
            __threadfence();
            st_rel(&g_fdone[b * NQ + quarter], 1);
        }
        return;
    }

    // ================= CONSUMER =================
    const int s0      = (blockIdx.y - NQ) * SPB;
    const int half    = tid >> 7;         // 0: si 0-7, 1: si 8-15
    const int h       = tid & 127;        // e-slot: floats [4h, 4h+4)
    const int quarter = s0 >> 7;

    __shared__ float tile[TCH * E_DIM];               // 32 KB staged rows
    __shared__ float smean[SPB];
    __shared__ float sstd[SPB];
    __shared__ unsigned long long sw2[SPB][TCH];      // packed (w,w)

    if (tid == 0) {
        while (!ld_acq(&g_fdone[b * NQ + quarter])) __nanosleep(64);
    }
    __syncthreads();

    if (tid < SPB) {
        float2 ms = g_ms[b * S_DIM + s0 + tid];
        smean[tid] = ms.x;
        sstd[tid]  = ms.y;
    }
    __syncthreads();

    // Warp-parallel union window (lane si=lane&15, shfl min/max reduce).
    int tlo, thi;
    {
        int si = lane & 15;
        float mean = smean[si];
        float hw   = sqrtf(CUT / sstd[si]);
        int lo = (int)fmaxf(0.0f, ceilf(mean - hw));
        int hi = (int)fminf((float)(T_DIM - 1), floorf(mean + hw));
        #pragma unroll
        for (int off = 8; off; off >>= 1) {
            lo = min(lo, __shfl_xor_sync(0xFFFFFFFFu, lo, off));
            hi = max(hi, __shfl_xor_sync(0xFFFFFFFFu, hi, off));
        }
        tlo = lo; thi = hi;
    }

    ulonglong2 acc[8];
    #pragma unroll
    for (int i = 0; i < 8; i++) { acc[i].x = acc[i].y = 0ull; }

    const unsigned tile_base = (unsigned)__cvta_generic_to_shared(tile);

    for (int tb = tlo; tb <= thi; tb += TCH) {
        int n = min(TCH, thi - tb + 1);
        __syncthreads();   // protect tile + sw2 reuse across chunks

        // Stage n rows (2 KB each) into shared: threads split row-pairs,
        // 16B per cp.async, all copies in flight at once.
        for (int j = half; j < n; j += 2) {
            const float* src = emb + ((size_t)(tb + j) * B_DIM + b) * E_DIM + h * 4;
            cp_async16(tile_base + (unsigned)(j * E_DIM + h * 4) * 4u, src);
        }
        asm volatile("cp.async.commit_group;" ::: "memory");

        // Weights (independent of staged data — overlaps the copies).
        {
            int si = tid >> 4;                // 0..15
            int tj = tid & (TCH - 1);
            float wv = 0.0f;
            if (tj < n) {
                int   t = tb + tj;
                float d = smean[si] - (float)t;
                wv = __expf(-sstd[si] * d * d) * mask[(size_t)t * B_DIM + b];
            }
            sw2[si][tj] = pack2f(wv, wv);
        }

        asm volatile("cp.async.wait_group 0;" ::: "memory");
        __syncthreads();

        // FMA entirely from shared: LDS.128 row slice + 8 broadcast LDS.64.
        #pragma unroll 4
        for (int j = 0; j < n; j++) {
            ulonglong2 v = *(const ulonglong2*)&tile[j * E_DIM + h * 4];
            #pragma unroll
            for (int r = 0; r < 8; r++) {
                unsigned long long w2 = sw2[half * 8 + r][j];
                acc[r].x = fma2(v.x, w2, acc[r].x);
                acc[r].y = fma2(v.y, w2, acc[r].y);
            }
        }
    }

    float* op = out_ctx + ((size_t)(s0 + half * 8) * B_DIM + b) * E_DIM + h * 4;
    #pragma unroll
    for (int r = 0; r < 8; r++) {
        *(ulonglong2*)op = acc[r];
        op += (size_t)B_DIM * E_DIM;
    }
}

// ---------------------------------------------------------------------------
extern "C" void kernel_launch(void* const* d_in, const int* in_sizes, int n_in,
                              void* d_out, int out_size) {
    const float* query = (const float*)d_in[0];  // [S,B,Q]
    const float* emb   = (const float*)d_in[1];  // [T,B,E]
    const float* mask  = (const float*)d_in[2];  // [T,B]
    const float* pos   = (const float*)d_in[3];  // [S,B]
    const float* W     = (const float*)d_in[4];  // [2,Q]
    const float* bias  = (const float*)d_in[5];  // [2]

    float* out_ctx  = (float*)d_out;                                  // [S,B,E]
    float* out_mean = (float*)d_out + (size_t)S_DIM * B_DIM * E_DIM;  // [S,B]

    dim3 grid(B_DIM, NQ + S_DIM / SPB);   // 128 producers, 1024 consumers
    ga_fused<<<grid, NTHR>>>(query, emb, mask, pos, W, bias, out_ctx, out_mean);
}